// round 13
// baseline (speedup 1.0000x reference)
#include <cuda_runtime.h>
#include <cuda_fp16.h>
#include <cstdint>

// ---------------------------------------------------------------------------
// GAT layer, algebraically reduced:
//   alpha[i,j] = adj[i,j]*E[j] / sum_j adj[i,j]*E[j],  E = exp(src)
//   out[b,i,:] = (adj @ (E*h_sum)) / (N * (adj @ E))
// cp.async-pipelined fp16 mma.sync GEMM, BM=64, 256 threads (8 warps:
// 4m x 2n, warp tile m16 x n40), 4 stages, 2 CTAs/SM for cross-CTA latency
// overlap and full-chip grid (256 CTAs). A fp32 staged raw, converted to
// fp16 fragments consumer-side. B fp16 in gmem.
// ---------------------------------------------------------------------------

#define BATCH 4
#define NNODE 4096
#define DD    256
#define NP    80            // 64 h_sum cols + 1 E col + 15 pad
#define BM    64
#define BK    32
#define STAGES 4
#define THREADS 256
#define SWA   40            // A smem row stride (words); banks conflict-free
#define SBB   80            // B smem row stride (bytes)
#define A_STG (BM * SWA * 4)          // 10240 B
#define B_STG (NP * SBB)              // 6400 B
#define OFF_B (STAGES * A_STG)        // 40960
#define OFF_Z (OFF_B + STAGES * B_STG)  // 66560
#define SMEM_TOTAL (OFF_Z + 512)      // 67072 B  (x2 CTAs = 134 KB/SM)

__device__ float  d_biasv[NP];
__device__ __align__(16) __half d_Mredh[NP * DD];          // [c][d] fp16
__device__ __align__(16) __half d_gh[BATCH * NP * NNODE];  // [b][c][j] fp16

// ------------------------------ helpers -----------------------------------
__device__ __forceinline__ unsigned su32(const void* p) {
    return (unsigned)__cvta_generic_to_shared(p);
}
__device__ __forceinline__ void cpa16(unsigned d, const void* s) {
    asm volatile("cp.async.cg.shared.global [%0], [%1], 16;\n" :: "r"(d), "l"(s));
}
__device__ __forceinline__ void cpcommit() {
    asm volatile("cp.async.commit_group;\n" ::);
}
template<int W> __device__ __forceinline__ void cpwait() {
    asm volatile("cp.async.wait_group %0;\n" :: "n"(W));
}
__device__ __forceinline__ unsigned pack2(float lo, float hi) {
    unsigned d;
    asm("cvt.rn.f16x2.f32 %0, %1, %2;" : "=r"(d) : "f"(hi), "f"(lo));
    return d;
}
__device__ __forceinline__ void ldsm4(unsigned* r, unsigned a) {
    asm volatile("ldmatrix.sync.aligned.m8n8.x4.shared.b16 {%0,%1,%2,%3}, [%4];"
                 : "=r"(r[0]), "=r"(r[1]), "=r"(r[2]), "=r"(r[3]) : "r"(a));
}
__device__ __forceinline__ void mma16(float* d, const unsigned* a, const unsigned* b) {
    asm volatile("mma.sync.aligned.m16n8k16.row.col.f32.f16.f16.f32 "
                 "{%0,%1,%2,%3}, {%4,%5,%6,%7}, {%8,%9}, {%0,%1,%2,%3};"
                 : "+f"(d[0]), "+f"(d[1]), "+f"(d[2]), "+f"(d[3])
                 : "r"(a[0]), "r"(a[1]), "r"(a[2]), "r"(a[3]),
                   "r"(b[0]), "r"(b[1]));
}

// ------------------------------ prep (wide) --------------------------------
// 17 blocks x 1024 threads.
// Blocks 0..15: 4 rows of Mredh each (c = blk*4 + tid/256, col = tid%256).
// Block 16: row 64 via 4-way split reduce; rows 65..79 zero; bias vector.
__global__ __launch_bounds__(1024)
void prep_kernel(const float* __restrict__ W_fc,
                 const float* __restrict__ b_fc,
                 const float* __restrict__ W_attn) {
    const int tid = threadIdx.x;
    const int blk = blockIdx.x;
    if (blk < 16) {
        int c = blk * 4 + (tid >> 8), col = tid & 255;
        float v = W_fc[c * DD + col] + W_fc[(64 + c) * DD + col] +
                  W_fc[(128 + c) * DD + col] + W_fc[(192 + c) * DD + col];
        d_Mredh[c * DD + col] = __float2half(v);
        return;
    }
    __shared__ float ws[256];
    __shared__ float part[4][256];
    if (tid < 256) {
        int h = tid >> 6, o = tid & 63;
        ws[tid] = 0.25f * (W_attn[       h * 128 + o] +
                           W_attn[ 512 + h * 128 + o] +
                           W_attn[1024 + h * 128 + o] +
                           W_attn[1536 + h * 128 + o]);
    }
    __syncthreads();
    {   // row-64 partial: quarter q sums 64 rows
        int q = tid >> 8, col = tid & 255;
        float v0 = 0.f, v1 = 0.f;
        #pragma unroll 8
        for (int r = q * 64; r < q * 64 + 64; r += 2) {
            v0 += W_fc[r * DD + col] * ws[r];
            v1 += W_fc[(r + 1) * DD + col] * ws[r + 1];
        }
        part[q][col] = v0 + v1;
    }
    // rows 65..79 zero (3840 halves = 1920 uints)
    for (int idx = tid; idx < 1920; idx += 1024)
        ((unsigned*)(d_Mredh + 65 * DD))[idx] = 0u;
    // simple bias entries
    if (tid >= 512 && tid < 576) {
        int o = tid - 512;
        d_biasv[o] = b_fc[o] + b_fc[64 + o] + b_fc[128 + o] + b_fc[192 + o];
    }
    if (tid >= 960 && tid < 975)
        d_biasv[65 + (tid - 960)] = 0.f;
    // bias[64] = ws . b_fc  (warp 8 shuffle-reduce)
    if (tid >= 256 && tid < 288) {
        int lane = tid - 256;
        float s = 0.f;
        #pragma unroll
        for (int r = lane; r < 256; r += 32) s += b_fc[r] * ws[r];
        #pragma unroll
        for (int off = 16; off > 0; off >>= 1)
            s += __shfl_xor_sync(0xFFFFFFFF, s, off);
        if (lane == 0) d_biasv[64] = s;
    }
    __syncthreads();
    if (tid < 256)
        d_Mredh[64 * DD + tid] =
            __float2half(part[0][tid] + part[1][tid] + part[2][tid] + part[3][tid]);
}

// --------------------- unified pipelined fp16 GEMM -------------------------
// MODE 0: proj: acc = features[16384x256] @ Mredh^T; epilogue adds bias,
//         computes E=exp(col64) and writes g fp16 to d_gh (transform fused).
// MODE 1: agg:  acc = adj[4096x4096] @ gh^T; epilogue normalizes by col 64.
template<int MODE>
__global__ __launch_bounds__(THREADS, 2)
void gemm_kernel(const float* __restrict__ Abase, float* __restrict__ OutP)
{
    constexpr int lda = MODE ? NNODE : DD;     // floats
    constexpr int ldb = MODE ? NNODE : DD;     // halves
    constexpr int KT  = MODE ? NNODE / BK : DD / BK;

    extern __shared__ __align__(16) char sm[];
    float* Zs = (float*)(sm + OFF_Z);

    const int mtile = blockIdx.x, batch = blockIdx.y;
    const int tid = threadIdx.x;
    const int wid = tid >> 5, lane = tid & 31;
    const int wm = wid & 3, wn = wid >> 2;     // 4 m-warps x 2 n-warps
    const int g = lane >> 2, t = lane & 3;

    const float* A = Abase + (MODE ? (long)batch * NNODE * NNODE : 0L)
                           + (long)mtile * BM * lda;
    const __half* Bh = MODE ? (d_gh + (long)batch * NP * NNODE) : d_Mredh;

    const int ar = tid >> 3, ac = tid & 7;     // A chunk coords (rows 0..31)
    const int br = tid >> 2, bc = tid & 3;     // B chunk coords

    auto issue = [&](int s, int kt) {
        char* as = sm + s * A_STG;
        const float* ag = A + (long)kt * BK;
        #pragma unroll
        for (int q = 0; q < 2; q++) {
            int r = q * 32 + ar;
            cpa16(su32(as + r * (SWA * 4) + ac * 16), ag + (long)r * lda + ac * 4);
        }
        char* bs = sm + OFF_B + s * B_STG;
        const __half* bg = Bh + (long)kt * BK;
        cpa16(su32(bs + br * SBB + bc * 16), bg + (long)br * ldb + bc * 8);
        if (tid < 64) {
            int r2 = 64 + (tid >> 2);
            cpa16(su32(bs + r2 * SBB + bc * 16), bg + (long)r2 * ldb + bc * 8);
        }
    };

    float acc[5][4] = {};

    auto compute = [&](int s) {
        const float* as = (const float*)(sm + s * A_STG);
        const char*  bs = sm + OFF_B + s * B_STG;
        unsigned af[2][4], bf[5][4];
        unsigned b0 = su32(bs + (wn * 40 + (lane & 7)) * SBB + (lane >> 3) * 16);
        #pragma unroll
        for (int j = 0; j < 5; j++) ldsm4(bf[j], b0 + j * 8 * SBB);
        const float* pr = as + (wm * 16 + g) * SWA + 2 * t;
        #pragma unroll
        for (int kh = 0; kh < 2; kh++) {
            const float* p = pr + kh * 16;
            float2 v0 = *(const float2*)(p);
            float2 v1 = *(const float2*)(p + 8 * SWA);
            float2 v2 = *(const float2*)(p + 8);
            float2 v3 = *(const float2*)(p + 8 * SWA + 8);
            af[kh][0] = pack2(v0.x, v0.y);
            af[kh][1] = pack2(v1.x, v1.y);
            af[kh][2] = pack2(v2.x, v2.y);
            af[kh][3] = pack2(v3.x, v3.y);
        }
        #pragma unroll
        for (int kh = 0; kh < 2; kh++)
            #pragma unroll
            for (int j = 0; j < 5; j++)
                mma16(acc[j], af[kh], bf[j] + kh * 2);
    };

    #pragma unroll
    for (int s = 0; s < STAGES - 1; s++) { issue(s, s); cpcommit(); }

    for (int k = 0; k < KT; k++) {
        cpwait<STAGES - 2>();
        __syncthreads();
        if (k + STAGES - 1 < KT) issue((k + STAGES - 1) % STAGES, k + STAGES - 1);
        cpcommit();
        compute(k % STAGES);
    }

    // ------------------------------ epilogues ------------------------------
    if (MODE == 0) {
        const float b64 = d_biasv[64];
        if (wn == 1 && t == 0) {
            Zs[wm * 16 + g]     = acc[3][0] + b64;
            Zs[wm * 16 + g + 8] = acc[3][2] + b64;
        }
        __syncthreads();
        const int bb = (mtile * BM) >> 12;
        const int jbase = (mtile * BM) & (NNODE - 1);
        __half* gb = d_gh + (long)bb * NP * NNODE;
        {
            int rl0 = wm * 16 + g;
            float E0 = __expf(Zs[rl0]);
            float E1 = __expf(Zs[rl0 + 8]);
            int j0 = jbase + rl0, j1 = j0 + 8;
            #pragma unroll
            for (int j = 0; j < 5; j++) {
                int colb = wn * 40 + j * 8 + 2 * t;
                if (colb < 64) {
                    float c0 = d_biasv[colb], c1 = d_biasv[colb + 1];
                    gb[(long)colb * NNODE + j0]       = __float2half(E0 * (acc[j][0] + c0));
                    gb[(long)(colb + 1) * NNODE + j0] = __float2half(E0 * (acc[j][1] + c1));
                    gb[(long)colb * NNODE + j1]       = __float2half(E1 * (acc[j][2] + c0));
                    gb[(long)(colb + 1) * NNODE + j1] = __float2half(E1 * (acc[j][3] + c1));
                } else if (colb == 64) {
                    gb[64L * NNODE + j0] = __float2half(E0);
                    gb[64L * NNODE + j1] = __float2half(E1);
                }
            }
        }
    } else {
        if (wn == 1 && t == 0) {
            Zs[wm * 16 + g]     = acc[3][0];
            Zs[wm * 16 + g + 8] = acc[3][2];
        }
        __syncthreads();
        {
            int rl0 = wm * 16 + g;
            float rz0 = 1.0f / (4096.0f * Zs[rl0]);
            float rz1 = 1.0f / (4096.0f * Zs[rl0 + 8]);
            long ro0 = ((long)batch * NNODE + mtile * BM + rl0) * 64;
            long ro1 = ro0 + 8 * 64;
            #pragma unroll
            for (int j = 0; j < 5; j++) {
                int colb = wn * 40 + j * 8 + 2 * t;
                if (colb < 64) {
                    *(float2*)(OutP + ro0 + colb) =
                        make_float2(acc[j][0] * rz0, acc[j][1] * rz0);
                    *(float2*)(OutP + ro1 + colb) =
                        make_float2(acc[j][2] * rz1, acc[j][3] * rz1);
                }
            }
        }
    }
}

// ------------------------------ launch ------------------------------------
extern "C" void kernel_launch(void* const* d_in, const int* in_sizes, int n_in,
                              void* d_out, int out_size) {
    const float* features = (const float*)d_in[0];
    const float* adj      = (const float*)d_in[1];
    const float* W_fc     = (const float*)d_in[2];
    const float* b_fc     = (const float*)d_in[3];
    const float* W_attn   = (const float*)d_in[4];
    float* out = (float*)d_out;

    cudaFuncSetAttribute(gemm_kernel<0>,
                         cudaFuncAttributeMaxDynamicSharedMemorySize, SMEM_TOTAL);
    cudaFuncSetAttribute(gemm_kernel<1>,
                         cudaFuncAttributeMaxDynamicSharedMemorySize, SMEM_TOTAL);

    prep_kernel<<<17, 1024>>>(W_fc, b_fc, W_attn);
    gemm_kernel<0><<<16384 / BM, THREADS, SMEM_TOTAL>>>(features, nullptr);
    gemm_kernel<1><<<dim3(NNODE / BM, BATCH), THREADS, SMEM_TOTAL>>>(adj, out);
}

// round 15
// speedup vs baseline: 1.0280x; 1.0280x over previous
#include <cuda_runtime.h>
#include <cuda_fp16.h>
#include <cstdint>

// ---------------------------------------------------------------------------
// GAT layer, algebraically reduced:
//   alpha[i,j] = adj[i,j]*E[j] / sum_j adj[i,j]*E[j],  E = exp(src)
//   out[b,i,:] = (adj @ (E*h_sum)) / (N * (adj @ E))
// R14: prep_kernel eliminated. proj_kernel computes ws/Mredh/bias in a smem
// prologue (B operand fully smem-resident for its 8 k-tiles); agg_kernel is
// the proven R12 config (BM=128, 512 thr, 4-stage cp.async, fp16 mma.sync).
// ---------------------------------------------------------------------------

#define BATCH 4
#define NNODE 4096
#define DD    256
#define NP    80            // 64 h_sum cols + 1 E col + 15 pad
#define BM    128
#define BK    32
#define STAGES 4
#define THREADS 512
#define SWA   40            // A smem row stride (words); banks conflict-free
#define SBB   80            // B smem row stride (bytes) [agg]
#define A_STG (BM * SWA * 4)          // 20480 B

// ---- agg smem map ----
#define B_STG (NP * SBB)              // 6400 B
#define OFF_B (STAGES * A_STG)        // 81920
#define OFF_Z (OFF_B + STAGES * B_STG)
#define SMEM_AGG (OFF_Z + 512)        // ~108 KB

// ---- proj smem map (B fully resident, 528 B/row) ----
#define PROW  528
#define POFF_B    (STAGES * A_STG)            // 81920
#define POFF_Z    (POFF_B + NP * PROW)        // 124160
#define POFF_WS   (POFF_Z + 512)              // 124672
#define POFF_PART (POFF_WS + 1024)            // 125696
#define POFF_BIAS (POFF_PART + 2048)          // 127744
#define SMEM_PROJ (POFF_BIAS + 384)           // 128128

__device__ __align__(16) __half d_gh[BATCH * NP * NNODE];  // [b][c][j] fp16

// ------------------------------ helpers -----------------------------------
__device__ __forceinline__ unsigned su32(const void* p) {
    return (unsigned)__cvta_generic_to_shared(p);
}
__device__ __forceinline__ void cpa16(unsigned d, const void* s) {
    asm volatile("cp.async.cg.shared.global [%0], [%1], 16;\n" :: "r"(d), "l"(s));
}
__device__ __forceinline__ void cpcommit() {
    asm volatile("cp.async.commit_group;\n" ::);
}
template<int W> __device__ __forceinline__ void cpwait() {
    asm volatile("cp.async.wait_group %0;\n" :: "n"(W));
}
__device__ __forceinline__ unsigned pack2(float lo, float hi) {
    unsigned d;
    asm("cvt.rn.f16x2.f32 %0, %1, %2;" : "=r"(d) : "f"(hi), "f"(lo));
    return d;
}
__device__ __forceinline__ void ldsm4(unsigned* r, unsigned a) {
    asm volatile("ldmatrix.sync.aligned.m8n8.x4.shared.b16 {%0,%1,%2,%3}, [%4];"
                 : "=r"(r[0]), "=r"(r[1]), "=r"(r[2]), "=r"(r[3]) : "r"(a));
}
__device__ __forceinline__ void mma16(float* d, const unsigned* a, const unsigned* b) {
    asm volatile("mma.sync.aligned.m16n8k16.row.col.f32.f16.f16.f32 "
                 "{%0,%1,%2,%3}, {%4,%5,%6,%7}, {%8,%9}, {%0,%1,%2,%3};"
                 : "+f"(d[0]), "+f"(d[1]), "+f"(d[2]), "+f"(d[3])
                 : "r"(a[0]), "r"(a[1]), "r"(a[2]), "r"(a[3]),
                   "r"(b[0]), "r"(b[1]));
}

// ---------------- proj: prologue-fused projection + transform --------------
// acc = features[16384x256] @ Mredh^T ; Mredh/bias computed in-CTA from
// W_fc/W_attn/b_fc; epilogue computes E=exp(col64+bias64) and writes g fp16.
__global__ __launch_bounds__(THREADS, 1)
void proj_kernel(const float* __restrict__ F,
                 const float* __restrict__ W_fc,
                 const float* __restrict__ b_fc,
                 const float* __restrict__ W_attn)
{
    constexpr int KT = DD / BK;                 // 8
    extern __shared__ __align__(16) char sm[];
    float*  Zs    = (float*)(sm + POFF_Z);
    float*  ws    = (float*)(sm + POFF_WS);
    float*  part  = (float*)(sm + POFF_PART);
    float*  biasv = (float*)(sm + POFF_BIAS);
    __half* Bf    = (__half*)(sm + POFF_B);     // row stride 264 halves

    const int mtile = blockIdx.x;
    const int tid = threadIdx.x;
    const int wid = tid >> 5, lane = tid & 31;
    const int wm = wid & 7, wn = wid >> 3;      // 8 m-warps x 2 n-warps
    const int g = lane >> 2, t = lane & 3;

    const float* A = F + (long)mtile * BM * DD;
    const int ar = tid >> 3, ac = tid & 7;

    auto issueA = [&](int s, int kt) {
        char* as = sm + s * A_STG;
        const float* ag = A + (long)kt * BK;
        #pragma unroll
        for (int q = 0; q < 2; q++) {
            int r = q * 64 + ar;
            cpa16(su32(as + r * (SWA * 4) + ac * 16), ag + (long)r * DD + ac * 4);
        }
    };

    // prefetch 3 A stages first so DRAM overlaps the prologue
    #pragma unroll
    for (int s = 0; s < STAGES - 1; s++) { issueA(s, s); cpcommit(); }

    // ---- prologue: ws, Mredh -> Bf, bias ----
    if (tid < 256) {
        int h = tid >> 6, o = tid & 63;
        ws[tid] = 0.25f * (W_attn[       h * 128 + o] +
                           W_attn[ 512 + h * 128 + o] +
                           W_attn[1024 + h * 128 + o] +
                           W_attn[1536 + h * 128 + o]);
    }
    __syncthreads();
    for (int idx = tid; idx < 64 * 256; idx += THREADS) {
        int c = idx >> 8, d = idx & 255;
        float v = W_fc[c * DD + d] + W_fc[(64 + c) * DD + d] +
                  W_fc[(128 + c) * DD + d] + W_fc[(192 + c) * DD + d];
        Bf[c * 264 + d] = __float2half(v);
    }
    for (int idx = tid; idx < 15 * 256; idx += THREADS) {
        int c = 65 + (idx >> 8), d = idx & 255;
        Bf[c * 264 + d] = __float2half(0.f);
    }
    {   // row 64: split the 256-dot across 2 halves per column
        int q = tid >> 8, col = tid & 255;
        float v0 = 0.f, v1 = 0.f;
        #pragma unroll 8
        for (int r = q * 128; r < q * 128 + 128; r += 2) {
            v0 += W_fc[r * DD + col] * ws[r];
            v1 += W_fc[(r + 1) * DD + col] * ws[r + 1];
        }
        part[q * 256 + col] = v0 + v1;
    }
    if (tid < 64) {
        biasv[tid] = b_fc[tid] + b_fc[64 + tid] +
                     b_fc[128 + tid] + b_fc[192 + tid];
    } else if (tid >= 65 && tid < 80) {
        biasv[tid] = 0.f;
    }
    if (tid >= 448 && tid < 480) {              // warp 14: bias[64]
        int l = tid - 448;
        float s = 0.f;
        #pragma unroll
        for (int r = l; r < 256; r += 32) s += b_fc[r] * ws[r];
        #pragma unroll
        for (int off = 16; off > 0; off >>= 1)
            s += __shfl_xor_sync(0xFFFFFFFF, s, off);
        if (l == 0) biasv[64] = s;
    }
    __syncthreads();
    if (tid < 256)
        Bf[64 * 264 + tid] = __float2half(part[tid] + part[256 + tid]);
    __syncthreads();

    // ---- main loop ----
    float acc[5][4] = {};
    for (int k = 0; k < KT; k++) {
        cpwait<STAGES - 2>();
        __syncthreads();
        if (k + STAGES - 1 < KT) issueA((k + STAGES - 1) % STAGES, k + STAGES - 1);
        cpcommit();
        const float* as = (const float*)(sm + (k % STAGES) * A_STG);
        unsigned af[2][4], bf[5][4];
        unsigned b0 = su32((char*)Bf + (wn * 40 + (lane & 7)) * PROW
                           + (lane >> 3) * 16 + k * 64);
        #pragma unroll
        for (int j = 0; j < 5; j++) ldsm4(bf[j], b0 + j * 8 * PROW);
        const float* pr = as + (wm * 16 + g) * SWA + 2 * t;
        #pragma unroll
        for (int kh = 0; kh < 2; kh++) {
            const float* p = pr + kh * 16;
            float2 v0 = *(const float2*)(p);
            float2 v1 = *(const float2*)(p + 8 * SWA);
            float2 v2 = *(const float2*)(p + 8);
            float2 v3 = *(const float2*)(p + 8 * SWA + 8);
            af[kh][0] = pack2(v0.x, v0.y);
            af[kh][1] = pack2(v1.x, v1.y);
            af[kh][2] = pack2(v2.x, v2.y);
            af[kh][3] = pack2(v3.x, v3.y);
        }
        #pragma unroll
        for (int kh = 0; kh < 2; kh++)
            #pragma unroll
            for (int j = 0; j < 5; j++)
                mma16(acc[j], af[kh], bf[j] + kh * 2);
    }

    // ---- epilogue: E from col 64, write g fp16 (transposed) ----
    const float b64 = biasv[64];
    if (wn == 1 && t == 0) {
        Zs[wm * 16 + g]     = acc[3][0] + b64;
        Zs[wm * 16 + g + 8] = acc[3][2] + b64;
    }
    __syncthreads();
    const int bb = (mtile * BM) >> 12;
    const int jbase = (mtile * BM) & (NNODE - 1);
    __half* gb = d_gh + (long)bb * NP * NNODE;
    {
        int rl0 = wm * 16 + g;
        float E0 = __expf(Zs[rl0]);
        float E1 = __expf(Zs[rl0 + 8]);
        int j0 = jbase + rl0, j1 = j0 + 8;
        #pragma unroll
        for (int j = 0; j < 5; j++) {
            int colb = wn * 40 + j * 8 + 2 * t;
            if (colb < 64) {
                float c0 = biasv[colb], c1 = biasv[colb + 1];
                gb[(long)colb * NNODE + j0]       = __float2half(E0 * (acc[j][0] + c0));
                gb[(long)(colb + 1) * NNODE + j0] = __float2half(E0 * (acc[j][1] + c1));
                gb[(long)colb * NNODE + j1]       = __float2half(E1 * (acc[j][2] + c0));
                gb[(long)(colb + 1) * NNODE + j1] = __float2half(E1 * (acc[j][3] + c1));
            } else if (colb == 64) {
                gb[64L * NNODE + j0] = __float2half(E0);
                gb[64L * NNODE + j1] = __float2half(E1);
            }
        }
    }
}

// --------------------------- agg (R12 config) -------------------------------
// out = (adj @ gh^T) / (N*Z), Z fused from column 64.
__global__ __launch_bounds__(THREADS, 1)
void agg_kernel(const float* __restrict__ Abase, float* __restrict__ OutP)
{
    constexpr int lda = NNODE;                 // floats
    constexpr int ldb = NNODE;                 // halves
    constexpr int KT  = NNODE / BK;            // 128

    extern __shared__ __align__(16) char sm[];
    float* Zs = (float*)(sm + OFF_Z);

    const int mtile = blockIdx.x, batch = blockIdx.y;
    const int tid = threadIdx.x;
    const int wid = tid >> 5, lane = tid & 31;
    const int wm = wid & 7, wn = wid >> 3;     // 8 m-warps x 2 n-warps
    const int g = lane >> 2, t = lane & 3;

    const float* A = Abase + (long)batch * NNODE * NNODE + (long)mtile * BM * lda;
    const __half* Bh = d_gh + (long)batch * NP * NNODE;

    const int ar = tid >> 3, ac = tid & 7;
    const int br = tid >> 2, bc = tid & 3;

    auto issue = [&](int s, int kt) {
        char* as = sm + s * A_STG;
        const float* ag = A + (long)kt * BK;
        #pragma unroll
        for (int q = 0; q < 2; q++) {
            int r = q * 64 + ar;
            cpa16(su32(as + r * (SWA * 4) + ac * 16), ag + (long)r * lda + ac * 4);
        }
        if (tid < 320) {
            char* bs = sm + OFF_B + s * B_STG;
            const __half* bg = Bh + (long)kt * BK;
            cpa16(su32(bs + br * SBB + bc * 16), bg + (long)br * ldb + bc * 8);
        }
    };

    float acc[5][4] = {};

    auto compute = [&](int s) {
        const float* as = (const float*)(sm + s * A_STG);
        const char*  bs = sm + OFF_B + s * B_STG;
        unsigned af[2][4], bf[5][4];
        unsigned b0 = su32(bs + (wn * 40 + (lane & 7)) * SBB + (lane >> 3) * 16);
        #pragma unroll
        for (int j = 0; j < 5; j++) ldsm4(bf[j], b0 + j * 8 * SBB);
        const float* pr = as + (wm * 16 + g) * SWA + 2 * t;
        #pragma unroll
        for (int kh = 0; kh < 2; kh++) {
            const float* p = pr + kh * 16;
            float2 v0 = *(const float2*)(p);
            float2 v1 = *(const float2*)(p + 8 * SWA);
            float2 v2 = *(const float2*)(p + 8);
            float2 v3 = *(const float2*)(p + 8 * SWA + 8);
            af[kh][0] = pack2(v0.x, v0.y);
            af[kh][1] = pack2(v1.x, v1.y);
            af[kh][2] = pack2(v2.x, v2.y);
            af[kh][3] = pack2(v3.x, v3.y);
        }
        #pragma unroll
        for (int kh = 0; kh < 2; kh++)
            #pragma unroll
            for (int j = 0; j < 5; j++)
                mma16(acc[j], af[kh], bf[j] + kh * 2);
    };

    #pragma unroll
    for (int s = 0; s < STAGES - 1; s++) { issue(s, s); cpcommit(); }

    for (int k = 0; k < KT; k++) {
        cpwait<STAGES - 2>();
        __syncthreads();
        if (k + STAGES - 1 < KT) issue((k + STAGES - 1) % STAGES, k + STAGES - 1);
        cpcommit();
        compute(k % STAGES);
    }

    if (wn == 1 && t == 0) {
        Zs[wm * 16 + g]     = acc[3][0];
        Zs[wm * 16 + g + 8] = acc[3][2];
    }
    __syncthreads();
    {
        int rl0 = wm * 16 + g;
        float rz0 = 1.0f / (4096.0f * Zs[rl0]);
        float rz1 = 1.0f / (4096.0f * Zs[rl0 + 8]);
        long ro0 = ((long)batch * NNODE + mtile * BM + rl0) * 64;
        long ro1 = ro0 + 8 * 64;
        #pragma unroll
        for (int j = 0; j < 5; j++) {
            int colb = wn * 40 + j * 8 + 2 * t;
            if (colb < 64) {
                *(float2*)(OutP + ro0 + colb) =
                    make_float2(acc[j][0] * rz0, acc[j][1] * rz0);
                *(float2*)(OutP + ro1 + colb) =
                    make_float2(acc[j][2] * rz1, acc[j][3] * rz1);
            }
        }
    }
}

// ------------------------------ launch ------------------------------------
extern "C" void kernel_launch(void* const* d_in, const int* in_sizes, int n_in,
                              void* d_out, int out_size) {
    const float* features = (const float*)d_in[0];
    const float* adj      = (const float*)d_in[1];
    const float* W_fc     = (const float*)d_in[2];
    const float* b_fc     = (const float*)d_in[3];
    const float* W_attn   = (const float*)d_in[4];
    float* out = (float*)d_out;

    cudaFuncSetAttribute(proj_kernel,
                         cudaFuncAttributeMaxDynamicSharedMemorySize, SMEM_PROJ);
    cudaFuncSetAttribute(agg_kernel,
                         cudaFuncAttributeMaxDynamicSharedMemorySize, SMEM_AGG);

    proj_kernel<<<16384 / BM, THREADS, SMEM_PROJ>>>(features, W_fc, b_fc, W_attn);
    agg_kernel<<<dim3(NNODE / BM, BATCH), THREADS, SMEM_AGG>>>(adj, out);
}

// round 16
// speedup vs baseline: 1.0964x; 1.0666x over previous
#include <cuda_runtime.h>
#include <cuda_fp16.h>
#include <cstdint>

// ---------------------------------------------------------------------------
// GAT layer, algebraically reduced:
//   alpha[i,j] = adj[i,j]*E[j] / sum_j adj[i,j]*E[j],  E = exp(src)
//   out[b,i,:] = (adj @ (E*h_sum)) / (N * (adj @ E))
// R16: agg uses a k-split warp layout (8 m-warps x 2 k-groups, each warp
// m16 x n80 x k16) -- A fragment duplication eliminated, smem crossbar
// traffic 93KB -> 77KB per k-tile. Partial accumulators reduced once at the
// epilogue through the retired stage-0 smem. proj unchanged (R14 config).
// ---------------------------------------------------------------------------

#define BATCH 4
#define NNODE 4096
#define DD    256
#define NP    80            // 64 h_sum cols + 1 E col + 15 pad
#define BM    128
#define BK    32
#define STAGES 4
#define THREADS 512
#define SWA   40            // A smem row stride (words); banks conflict-free
#define SBB   80            // B smem row stride (bytes)
#define A_STG (BM * SWA * 4)          // 20480 B

// ---- agg smem map ----
#define B_STG (NP * SBB)              // 6400 B
#define OFF_B (STAGES * A_STG)        // 81920
#define OFF_Z (OFF_B + STAGES * B_STG)
#define SMEM_AGG (OFF_Z + 512)        // ~108 KB

// ---- proj smem map (B fully resident, 528 B/row) ----
#define PROW  528
#define POFF_B    (STAGES * A_STG)            // 81920
#define POFF_Z    (POFF_B + NP * PROW)        // 124160
#define POFF_WS   (POFF_Z + 512)              // 124672
#define POFF_PART (POFF_WS + 1024)            // 125696
#define POFF_BIAS (POFF_PART + 2048)          // 127744
#define SMEM_PROJ (POFF_BIAS + 384)           // 128128

__device__ __align__(16) __half d_gh[BATCH * NP * NNODE];  // [b][c][j] fp16

// ------------------------------ helpers -----------------------------------
__device__ __forceinline__ unsigned su32(const void* p) {
    return (unsigned)__cvta_generic_to_shared(p);
}
__device__ __forceinline__ void cpa16(unsigned d, const void* s) {
    asm volatile("cp.async.cg.shared.global [%0], [%1], 16;\n" :: "r"(d), "l"(s));
}
__device__ __forceinline__ void cpcommit() {
    asm volatile("cp.async.commit_group;\n" ::);
}
template<int W> __device__ __forceinline__ void cpwait() {
    asm volatile("cp.async.wait_group %0;\n" :: "n"(W));
}
__device__ __forceinline__ unsigned pack2(float lo, float hi) {
    unsigned d;
    asm("cvt.rn.f16x2.f32 %0, %1, %2;" : "=r"(d) : "f"(hi), "f"(lo));
    return d;
}
__device__ __forceinline__ void ldsm4(unsigned* r, unsigned a) {
    asm volatile("ldmatrix.sync.aligned.m8n8.x4.shared.b16 {%0,%1,%2,%3}, [%4];"
                 : "=r"(r[0]), "=r"(r[1]), "=r"(r[2]), "=r"(r[3]) : "r"(a));
}
__device__ __forceinline__ void mma16(float* d, const unsigned* a, const unsigned* b) {
    asm volatile("mma.sync.aligned.m16n8k16.row.col.f32.f16.f16.f32 "
                 "{%0,%1,%2,%3}, {%4,%5,%6,%7}, {%8,%9}, {%0,%1,%2,%3};"
                 : "+f"(d[0]), "+f"(d[1]), "+f"(d[2]), "+f"(d[3])
                 : "r"(a[0]), "r"(a[1]), "r"(a[2]), "r"(a[3]),
                   "r"(b[0]), "r"(b[1]));
}

// ---------------- proj: prologue-fused projection + transform --------------
__global__ __launch_bounds__(THREADS, 1)
void proj_kernel(const float* __restrict__ F,
                 const float* __restrict__ W_fc,
                 const float* __restrict__ b_fc,
                 const float* __restrict__ W_attn)
{
    constexpr int KT = DD / BK;                 // 8
    extern __shared__ __align__(16) char sm[];
    float*  Zs    = (float*)(sm + POFF_Z);
    float*  ws    = (float*)(sm + POFF_WS);
    float*  part  = (float*)(sm + POFF_PART);
    float*  biasv = (float*)(sm + POFF_BIAS);
    __half* Bf    = (__half*)(sm + POFF_B);     // row stride 264 halves

    const int mtile = blockIdx.x;
    const int tid = threadIdx.x;
    const int wid = tid >> 5, lane = tid & 31;
    const int wm = wid & 7, wn = wid >> 3;      // 8 m-warps x 2 n-warps
    const int g = lane >> 2, t = lane & 3;

    const float* A = F + (long)mtile * BM * DD;
    const int ar = tid >> 3, ac = tid & 7;

    auto issueA = [&](int s, int kt) {
        char* as = sm + s * A_STG;
        const float* ag = A + (long)kt * BK;
        #pragma unroll
        for (int q = 0; q < 2; q++) {
            int r = q * 64 + ar;
            cpa16(su32(as + r * (SWA * 4) + ac * 16), ag + (long)r * DD + ac * 4);
        }
    };

    #pragma unroll
    for (int s = 0; s < STAGES - 1; s++) { issueA(s, s); cpcommit(); }

    // ---- prologue: ws, Mredh -> Bf, bias ----
    if (tid < 256) {
        int h = tid >> 6, o = tid & 63;
        ws[tid] = 0.25f * (W_attn[       h * 128 + o] +
                           W_attn[ 512 + h * 128 + o] +
                           W_attn[1024 + h * 128 + o] +
                           W_attn[1536 + h * 128 + o]);
    }
    __syncthreads();
    for (int idx = tid; idx < 64 * 256; idx += THREADS) {
        int c = idx >> 8, d = idx & 255;
        float v = W_fc[c * DD + d] + W_fc[(64 + c) * DD + d] +
                  W_fc[(128 + c) * DD + d] + W_fc[(192 + c) * DD + d];
        Bf[c * 264 + d] = __float2half(v);
    }
    for (int idx = tid; idx < 15 * 256; idx += THREADS) {
        int c = 65 + (idx >> 8), d = idx & 255;
        Bf[c * 264 + d] = __float2half(0.f);
    }
    {
        int q = tid >> 8, col = tid & 255;
        float v0 = 0.f, v1 = 0.f;
        #pragma unroll 8
        for (int r = q * 128; r < q * 128 + 128; r += 2) {
            v0 += W_fc[r * DD + col] * ws[r];
            v1 += W_fc[(r + 1) * DD + col] * ws[r + 1];
        }
        part[q * 256 + col] = v0 + v1;
    }
    if (tid < 64) {
        biasv[tid] = b_fc[tid] + b_fc[64 + tid] +
                     b_fc[128 + tid] + b_fc[192 + tid];
    } else if (tid >= 65 && tid < 80) {
        biasv[tid] = 0.f;
    }
    if (tid >= 448 && tid < 480) {
        int l = tid - 448;
        float s = 0.f;
        #pragma unroll
        for (int r = l; r < 256; r += 32) s += b_fc[r] * ws[r];
        #pragma unroll
        for (int off = 16; off > 0; off >>= 1)
            s += __shfl_xor_sync(0xFFFFFFFF, s, off);
        if (l == 0) biasv[64] = s;
    }
    __syncthreads();
    if (tid < 256)
        Bf[64 * 264 + tid] = __float2half(part[tid] + part[256 + tid]);
    __syncthreads();

    // ---- main loop ----
    float acc[5][4] = {};
    for (int k = 0; k < KT; k++) {
        cpwait<STAGES - 2>();
        __syncthreads();
        if (k + STAGES - 1 < KT) issueA((k + STAGES - 1) % STAGES, k + STAGES - 1);
        cpcommit();
        const float* as = (const float*)(sm + (k % STAGES) * A_STG);
        unsigned af[2][4], bf[5][4];
        unsigned b0 = su32((char*)Bf + (wn * 40 + (lane & 7)) * PROW
                           + (lane >> 3) * 16 + k * 64);
        #pragma unroll
        for (int j = 0; j < 5; j++) ldsm4(bf[j], b0 + j * 8 * PROW);
        const float* pr = as + (wm * 16 + g) * SWA + 2 * t;
        #pragma unroll
        for (int kh = 0; kh < 2; kh++) {
            const float* p = pr + kh * 16;
            float2 v0 = *(const float2*)(p);
            float2 v1 = *(const float2*)(p + 8 * SWA);
            float2 v2 = *(const float2*)(p + 8);
            float2 v3 = *(const float2*)(p + 8 * SWA + 8);
            af[kh][0] = pack2(v0.x, v0.y);
            af[kh][1] = pack2(v1.x, v1.y);
            af[kh][2] = pack2(v2.x, v2.y);
            af[kh][3] = pack2(v3.x, v3.y);
        }
        #pragma unroll
        for (int kh = 0; kh < 2; kh++)
            #pragma unroll
            for (int j = 0; j < 5; j++)
                mma16(acc[j], af[kh], bf[j] + kh * 2);
    }

    // ---- epilogue: E from col 64, write g fp16 (transposed) ----
    const float b64 = biasv[64];
    if (wn == 1 && t == 0) {
        Zs[wm * 16 + g]     = acc[3][0] + b64;
        Zs[wm * 16 + g + 8] = acc[3][2] + b64;
    }
    __syncthreads();
    const int bb = (mtile * BM) >> 12;
    const int jbase = (mtile * BM) & (NNODE - 1);
    __half* gb = d_gh + (long)bb * NP * NNODE;
    {
        int rl0 = wm * 16 + g;
        float E0 = __expf(Zs[rl0]);
        float E1 = __expf(Zs[rl0 + 8]);
        int j0 = jbase + rl0, j1 = j0 + 8;
        #pragma unroll
        for (int j = 0; j < 5; j++) {
            int colb = wn * 40 + j * 8 + 2 * t;
            if (colb < 64) {
                float c0 = biasv[colb], c1 = biasv[colb + 1];
                gb[(long)colb * NNODE + j0]       = __float2half(E0 * (acc[j][0] + c0));
                gb[(long)(colb + 1) * NNODE + j0] = __float2half(E0 * (acc[j][1] + c1));
                gb[(long)colb * NNODE + j1]       = __float2half(E1 * (acc[j][2] + c0));
                gb[(long)(colb + 1) * NNODE + j1] = __float2half(E1 * (acc[j][3] + c1));
            } else if (colb == 64) {
                gb[64L * NNODE + j0] = __float2half(E0);
                gb[64L * NNODE + j1] = __float2half(E1);
            }
        }
    }
}

// --------------------------- agg: k-split warps ----------------------------
// out = (adj @ gh^T) / (N*Z). 16 warps = 8 m-warps x 2 k-groups; each warp
// computes m16 x n80 over its k16 half; partials reduced in the epilogue.
__global__ __launch_bounds__(THREADS, 1)
void agg_kernel(const float* __restrict__ Abase, float* __restrict__ OutP)
{
    constexpr int lda = NNODE;                 // floats
    constexpr int ldb = NNODE;                 // halves
    constexpr int KT  = NNODE / BK;            // 128

    extern __shared__ __align__(16) char sm[];
    float* Zs = (float*)(sm + OFF_Z);

    const int mtile = blockIdx.x, batch = blockIdx.y;
    const int tid = threadIdx.x;
    const int wid = tid >> 5, lane = tid & 31;
    const int wm = wid & 7, kq = wid >> 3;     // 8 m-warps x 2 k-groups
    const int g = lane >> 2, t = lane & 3;

    const float* A = Abase + (long)batch * NNODE * NNODE + (long)mtile * BM * lda;
    const __half* Bh = d_gh + (long)batch * NP * NNODE;

    const int ar = tid >> 3, ac = tid & 7;
    const int br = tid >> 2, bc = tid & 3;

    auto issue = [&](int s, int kt) {
        char* as = sm + s * A_STG;
        const float* ag = A + (long)kt * BK;
        #pragma unroll
        for (int q = 0; q < 2; q++) {
            int r = q * 64 + ar;
            cpa16(su32(as + r * (SWA * 4) + ac * 16), ag + (long)r * lda + ac * 4);
        }
        if (tid < 320) {
            char* bs = sm + OFF_B + s * B_STG;
            const __half* bg = Bh + (long)kt * BK;
            cpa16(su32(bs + br * SBB + bc * 16), bg + (long)br * ldb + bc * 8);
        }
    };

    float acc[10][4] = {};

    // B ldsm address: two n8 groups x k16(kq half) per ldsm4
    const int brow = (lane & 7) + ((lane >> 4) << 3);
    const int bkof = kq * 32 + (((lane >> 3) & 1) << 4);

    auto compute = [&](int s) {
        const float* as = (const float*)(sm + s * A_STG);
        const char*  bs = sm + OFF_B + s * B_STG;
        unsigned af[4], bf[5][4];
        unsigned b0 = su32(bs + brow * SBB + bkof);
        #pragma unroll
        for (int jj = 0; jj < 5; jj++) ldsm4(bf[jj], b0 + jj * 16 * SBB);
        const float* pr = as + (wm * 16 + g) * SWA + kq * 16 + 2 * t;
        {
            float2 v0 = *(const float2*)(pr);
            float2 v1 = *(const float2*)(pr + 8 * SWA);
            float2 v2 = *(const float2*)(pr + 8);
            float2 v3 = *(const float2*)(pr + 8 * SWA + 8);
            af[0] = pack2(v0.x, v0.y);
            af[1] = pack2(v1.x, v1.y);
            af[2] = pack2(v2.x, v2.y);
            af[3] = pack2(v3.x, v3.y);
        }
        #pragma unroll
        for (int jj = 0; jj < 5; jj++) {
            mma16(acc[2 * jj],     af, bf[jj]);        // cols jj*16 + 0..7
            mma16(acc[2 * jj + 1], af, bf[jj] + 2);    // cols jj*16 + 8..15
        }
    };

    #pragma unroll
    for (int s = 0; s < STAGES - 1; s++) { issue(s, s); cpcommit(); }

    for (int k = 0; k < KT; k++) {
        cpwait<STAGES - 2>();
        __syncthreads();
        if (k + STAGES - 1 < KT) issue((k + STAGES - 1) % STAGES, k + STAGES - 1);
        cpcommit();
        compute(k % STAGES);
    }

    // ---- k-partial reduction through retired stage smem ----
    float* red = (float*)sm;                   // 128 x 80 fp32 = 40KB
    __syncthreads();                           // all cp.async consumed; safe
    if (kq == 1) {
        #pragma unroll
        for (int c = 0; c < 10; c++) {
            #pragma unroll
            for (int q = 0; q < 4; q++) {
                int row = wm * 16 + g + ((q >> 1) << 3);
                int col = c * 8 + 2 * t + (q & 1);
                red[row * 80 + col] = acc[c][q];
            }
        }
    }
    __syncthreads();
    if (kq == 0) {
        #pragma unroll
        for (int c = 0; c < 10; c++) {
            #pragma unroll
            for (int q = 0; q < 4; q++) {
                int row = wm * 16 + g + ((q >> 1) << 3);
                int col = c * 8 + 2 * t + (q & 1);
                acc[c][q] += red[row * 80 + col];
            }
        }
        // Z from col 64 (c=8, q even, t==0)
        if (t == 0) {
            Zs[wm * 16 + g]     = acc[8][0];
            Zs[wm * 16 + g + 8] = acc[8][2];
        }
    }
    __syncthreads();
    if (kq == 0) {
        int rl0 = wm * 16 + g;
        float rz0 = 1.0f / (4096.0f * Zs[rl0]);
        float rz1 = 1.0f / (4096.0f * Zs[rl0 + 8]);
        long ro0 = ((long)batch * NNODE + mtile * BM + rl0) * 64;
        long ro1 = ro0 + 8 * 64;
        #pragma unroll
        for (int c = 0; c < 8; c++) {
            int colb = c * 8 + 2 * t;
            *(float2*)(OutP + ro0 + colb) =
                make_float2(acc[c][0] * rz0, acc[c][1] * rz0);
            *(float2*)(OutP + ro1 + colb) =
                make_float2(acc[c][2] * rz1, acc[c][3] * rz1);
        }
    }
}

// ------------------------------ launch ------------------------------------
extern "C" void kernel_launch(void* const* d_in, const int* in_sizes, int n_in,
                              void* d_out, int out_size) {
    const float* features = (const float*)d_in[0];
    const float* adj      = (const float*)d_in[1];
    const float* W_fc     = (const float*)d_in[2];
    const float* b_fc     = (const float*)d_in[3];
    const float* W_attn   = (const float*)d_in[4];
    float* out = (float*)d_out;

    cudaFuncSetAttribute(proj_kernel,
                         cudaFuncAttributeMaxDynamicSharedMemorySize, SMEM_PROJ);
    cudaFuncSetAttribute(agg_kernel,
                         cudaFuncAttributeMaxDynamicSharedMemorySize, SMEM_AGG);

    proj_kernel<<<16384 / BM, THREADS, SMEM_PROJ>>>(features, W_fc, b_fc, W_attn);
    agg_kernel<<<dim3(NNODE / BM, BATCH), THREADS, SMEM_AGG>>>(adj, out);
}

// round 17
// speedup vs baseline: 1.1261x; 1.0270x over previous
#include <cuda_runtime.h>
#include <cuda_fp16.h>
#include <cstdint>

// ---------------------------------------------------------------------------
// GAT layer, algebraically reduced:
//   alpha[i,j] = adj[i,j]*E[j] / sum_j adj[i,j]*E[j],  E = exp(src)
//   out[b,i,:] = (adj @ (E*h_sum)) / (N * (adj @ E))
// R17: agg processes TWO k-tiles per barrier (STAGES=6 as 3 double-stages,
// cp.async committed per pair) -- barrier count halved, tile k+1 fragment
// loads overlap tile k mma. k-split warp layout (8m x 2kq) kept from R16.
// proj unchanged (R14 config, own 4-stage smem map).
// ---------------------------------------------------------------------------

#define BATCH 4
#define NNODE 4096
#define DD    256
#define NP    80            // 64 h_sum cols + 1 E col + 15 pad
#define BM    128
#define BK    32
#define THREADS 512
#define SWA   40            // A smem row stride (words); banks conflict-free
#define SBB   80            // B smem row stride (bytes)
#define A_STG (BM * SWA * 4)          // 20480 B
#define B_STG (NP * SBB)              // 6400 B

// ---- agg smem map (6 stages) ----
#define ASTAGES 6
#define OFF_B (ASTAGES * A_STG)               // 122880
#define OFF_Z (OFF_B + ASTAGES * B_STG)       // 161280
#define SMEM_AGG (OFF_Z + 512)                // 161792 B

// ---- proj smem map (4 stages, B fully resident, 528 B/row) ----
#define PSTAGES 4
#define PROW  528
#define POFF_B    (PSTAGES * A_STG)           // 81920
#define POFF_Z    (POFF_B + NP * PROW)        // 124160
#define POFF_WS   (POFF_Z + 512)              // 124672
#define POFF_PART (POFF_WS + 1024)            // 125696
#define POFF_BIAS (POFF_PART + 2048)          // 127744
#define SMEM_PROJ (POFF_BIAS + 384)           // 128128

__device__ __align__(16) __half d_gh[BATCH * NP * NNODE];  // [b][c][j] fp16

// ------------------------------ helpers -----------------------------------
__device__ __forceinline__ unsigned su32(const void* p) {
    return (unsigned)__cvta_generic_to_shared(p);
}
__device__ __forceinline__ void cpa16(unsigned d, const void* s) {
    asm volatile("cp.async.cg.shared.global [%0], [%1], 16;\n" :: "r"(d), "l"(s));
}
__device__ __forceinline__ void cpcommit() {
    asm volatile("cp.async.commit_group;\n" ::);
}
template<int W> __device__ __forceinline__ void cpwait() {
    asm volatile("cp.async.wait_group %0;\n" :: "n"(W));
}
__device__ __forceinline__ unsigned pack2(float lo, float hi) {
    unsigned d;
    asm("cvt.rn.f16x2.f32 %0, %1, %2;" : "=r"(d) : "f"(hi), "f"(lo));
    return d;
}
__device__ __forceinline__ void ldsm4(unsigned* r, unsigned a) {
    asm volatile("ldmatrix.sync.aligned.m8n8.x4.shared.b16 {%0,%1,%2,%3}, [%4];"
                 : "=r"(r[0]), "=r"(r[1]), "=r"(r[2]), "=r"(r[3]) : "r"(a));
}
__device__ __forceinline__ void mma16(float* d, const unsigned* a, const unsigned* b) {
    asm volatile("mma.sync.aligned.m16n8k16.row.col.f32.f16.f16.f32 "
                 "{%0,%1,%2,%3}, {%4,%5,%6,%7}, {%8,%9}, {%0,%1,%2,%3};"
                 : "+f"(d[0]), "+f"(d[1]), "+f"(d[2]), "+f"(d[3])
                 : "r"(a[0]), "r"(a[1]), "r"(a[2]), "r"(a[3]),
                   "r"(b[0]), "r"(b[1]));
}

// ---------------- proj: prologue-fused projection + transform --------------
__global__ __launch_bounds__(THREADS, 1)
void proj_kernel(const float* __restrict__ F,
                 const float* __restrict__ W_fc,
                 const float* __restrict__ b_fc,
                 const float* __restrict__ W_attn)
{
    constexpr int KT = DD / BK;                 // 8
    extern __shared__ __align__(16) char sm[];
    float*  Zs    = (float*)(sm + POFF_Z);
    float*  ws    = (float*)(sm + POFF_WS);
    float*  part  = (float*)(sm + POFF_PART);
    float*  biasv = (float*)(sm + POFF_BIAS);
    __half* Bf    = (__half*)(sm + POFF_B);     // row stride 264 halves

    const int mtile = blockIdx.x;
    const int tid = threadIdx.x;
    const int wid = tid >> 5, lane = tid & 31;
    const int wm = wid & 7, wn = wid >> 3;      // 8 m-warps x 2 n-warps
    const int g = lane >> 2, t = lane & 3;

    const float* A = F + (long)mtile * BM * DD;
    const int ar = tid >> 3, ac = tid & 7;

    auto issueA = [&](int s, int kt) {
        char* as = sm + s * A_STG;
        const float* ag = A + (long)kt * BK;
        #pragma unroll
        for (int q = 0; q < 2; q++) {
            int r = q * 64 + ar;
            cpa16(su32(as + r * (SWA * 4) + ac * 16), ag + (long)r * DD + ac * 4);
        }
    };

    #pragma unroll
    for (int s = 0; s < PSTAGES - 1; s++) { issueA(s, s); cpcommit(); }

    // ---- prologue: ws, Mredh -> Bf, bias ----
    if (tid < 256) {
        int h = tid >> 6, o = tid & 63;
        ws[tid] = 0.25f * (W_attn[       h * 128 + o] +
                           W_attn[ 512 + h * 128 + o] +
                           W_attn[1024 + h * 128 + o] +
                           W_attn[1536 + h * 128 + o]);
    }
    __syncthreads();
    for (int idx = tid; idx < 64 * 256; idx += THREADS) {
        int c = idx >> 8, d = idx & 255;
        float v = W_fc[c * DD + d] + W_fc[(64 + c) * DD + d] +
                  W_fc[(128 + c) * DD + d] + W_fc[(192 + c) * DD + d];
        Bf[c * 264 + d] = __float2half(v);
    }
    for (int idx = tid; idx < 15 * 256; idx += THREADS) {
        int c = 65 + (idx >> 8), d = idx & 255;
        Bf[c * 264 + d] = __float2half(0.f);
    }
    {
        int q = tid >> 8, col = tid & 255;
        float v0 = 0.f, v1 = 0.f;
        #pragma unroll 8
        for (int r = q * 128; r < q * 128 + 128; r += 2) {
            v0 += W_fc[r * DD + col] * ws[r];
            v1 += W_fc[(r + 1) * DD + col] * ws[r + 1];
        }
        part[q * 256 + col] = v0 + v1;
    }
    if (tid < 64) {
        biasv[tid] = b_fc[tid] + b_fc[64 + tid] +
                     b_fc[128 + tid] + b_fc[192 + tid];
    } else if (tid >= 65 && tid < 80) {
        biasv[tid] = 0.f;
    }
    if (tid >= 448 && tid < 480) {
        int l = tid - 448;
        float s = 0.f;
        #pragma unroll
        for (int r = l; r < 256; r += 32) s += b_fc[r] * ws[r];
        #pragma unroll
        for (int off = 16; off > 0; off >>= 1)
            s += __shfl_xor_sync(0xFFFFFFFF, s, off);
        if (l == 0) biasv[64] = s;
    }
    __syncthreads();
    if (tid < 256)
        Bf[64 * 264 + tid] = __float2half(part[tid] + part[256 + tid]);
    __syncthreads();

    // ---- main loop ----
    float acc[5][4] = {};
    for (int k = 0; k < KT; k++) {
        cpwait<PSTAGES - 2>();
        __syncthreads();
        if (k + PSTAGES - 1 < KT) issueA((k + PSTAGES - 1) % PSTAGES, k + PSTAGES - 1);
        cpcommit();
        const float* as = (const float*)(sm + (k % PSTAGES) * A_STG);
        unsigned af[2][4], bf[5][4];
        unsigned b0 = su32((char*)Bf + (wn * 40 + (lane & 7)) * PROW
                           + (lane >> 3) * 16 + k * 64);
        #pragma unroll
        for (int j = 0; j < 5; j++) ldsm4(bf[j], b0 + j * 8 * PROW);
        const float* pr = as + (wm * 16 + g) * SWA + 2 * t;
        #pragma unroll
        for (int kh = 0; kh < 2; kh++) {
            const float* p = pr + kh * 16;
            float2 v0 = *(const float2*)(p);
            float2 v1 = *(const float2*)(p + 8 * SWA);
            float2 v2 = *(const float2*)(p + 8);
            float2 v3 = *(const float2*)(p + 8 * SWA + 8);
            af[kh][0] = pack2(v0.x, v0.y);
            af[kh][1] = pack2(v1.x, v1.y);
            af[kh][2] = pack2(v2.x, v2.y);
            af[kh][3] = pack2(v3.x, v3.y);
        }
        #pragma unroll
        for (int kh = 0; kh < 2; kh++)
            #pragma unroll
            for (int j = 0; j < 5; j++)
                mma16(acc[j], af[kh], bf[j] + kh * 2);
    }

    // ---- epilogue: E from col 64, write g fp16 (transposed) ----
    const float b64 = biasv[64];
    if (wn == 1 && t == 0) {
        Zs[wm * 16 + g]     = acc[3][0] + b64;
        Zs[wm * 16 + g + 8] = acc[3][2] + b64;
    }
    __syncthreads();
    const int bb = (mtile * BM) >> 12;
    const int jbase = (mtile * BM) & (NNODE - 1);
    __half* gb = d_gh + (long)bb * NP * NNODE;
    {
        int rl0 = wm * 16 + g;
        float E0 = __expf(Zs[rl0]);
        float E1 = __expf(Zs[rl0 + 8]);
        int j0 = jbase + rl0, j1 = j0 + 8;
        #pragma unroll
        for (int j = 0; j < 5; j++) {
            int colb = wn * 40 + j * 8 + 2 * t;
            if (colb < 64) {
                float c0 = biasv[colb], c1 = biasv[colb + 1];
                gb[(long)colb * NNODE + j0]       = __float2half(E0 * (acc[j][0] + c0));
                gb[(long)(colb + 1) * NNODE + j0] = __float2half(E0 * (acc[j][1] + c1));
                gb[(long)colb * NNODE + j1]       = __float2half(E1 * (acc[j][2] + c0));
                gb[(long)(colb + 1) * NNODE + j1] = __float2half(E1 * (acc[j][3] + c1));
            } else if (colb == 64) {
                gb[64L * NNODE + j0] = __float2half(E0);
                gb[64L * NNODE + j1] = __float2half(E1);
            }
        }
    }
}

// --------------------- agg: k-split warps, paired tiles --------------------
// out = (adj @ gh^T) / (N*Z). 16 warps = 8 m-warps x 2 k-groups; each warp
// m16 x n80 x k16. Two k-tiles per barrier; cp.async committed per pair.
__global__ __launch_bounds__(THREADS, 1)
void agg_kernel(const float* __restrict__ Abase, float* __restrict__ OutP)
{
    constexpr int lda = NNODE;                 // floats
    constexpr int ldb = NNODE;                 // halves
    constexpr int KT  = NNODE / BK;            // 128

    extern __shared__ __align__(16) char sm[];
    float* Zs = (float*)(sm + OFF_Z);

    const int mtile = blockIdx.x, batch = blockIdx.y;
    const int tid = threadIdx.x;
    const int wid = tid >> 5, lane = tid & 31;
    const int wm = wid & 7, kq = wid >> 3;     // 8 m-warps x 2 k-groups
    const int g = lane >> 2, t = lane & 3;

    const float* A = Abase + (long)batch * NNODE * NNODE + (long)mtile * BM * lda;
    const __half* Bh = d_gh + (long)batch * NP * NNODE;

    const int ar = tid >> 3, ac = tid & 7;
    const int br = tid >> 2, bc = tid & 3;

    auto issue = [&](int s, int kt) {
        char* as = sm + s * A_STG;
        const float* ag = A + (long)kt * BK;
        #pragma unroll
        for (int q = 0; q < 2; q++) {
            int r = q * 64 + ar;
            cpa16(su32(as + r * (SWA * 4) + ac * 16), ag + (long)r * lda + ac * 4);
        }
        if (tid < 320) {
            char* bs = sm + OFF_B + s * B_STG;
            const __half* bg = Bh + (long)kt * BK;
            cpa16(su32(bs + br * SBB + bc * 16), bg + (long)br * ldb + bc * 8);
        }
    };

    float acc[10][4] = {};

    const int brow = (lane & 7) + ((lane >> 4) << 3);
    const int bkof = kq * 32 + (((lane >> 3) & 1) << 4);

    auto compute = [&](int s) {
        const float* as = (const float*)(sm + s * A_STG);
        const char*  bs = sm + OFF_B + s * B_STG;
        unsigned af[4], bf[5][4];
        unsigned b0 = su32(bs + brow * SBB + bkof);
        #pragma unroll
        for (int jj = 0; jj < 5; jj++) ldsm4(bf[jj], b0 + jj * 16 * SBB);
        const float* pr = as + (wm * 16 + g) * SWA + kq * 16 + 2 * t;
        {
            float2 v0 = *(const float2*)(pr);
            float2 v1 = *(const float2*)(pr + 8 * SWA);
            float2 v2 = *(const float2*)(pr + 8);
            float2 v3 = *(const float2*)(pr + 8 * SWA + 8);
            af[0] = pack2(v0.x, v0.y);
            af[1] = pack2(v1.x, v1.y);
            af[2] = pack2(v2.x, v2.y);
            af[3] = pack2(v3.x, v3.y);
        }
        #pragma unroll
        for (int jj = 0; jj < 5; jj++) {
            mma16(acc[2 * jj],     af, bf[jj]);        // cols jj*16 + 0..7
            mma16(acc[2 * jj + 1], af, bf[jj] + 2);    // cols jj*16 + 8..15
        }
    };

    // prologue: 2 pairs (tiles 0..3), one commit per pair
    issue(0, 0); issue(1, 1); cpcommit();
    issue(2, 2); issue(3, 3); cpcommit();

    for (int k = 0; k < KT; k += 2) {
        cpwait<1>();
        __syncthreads();
        if (k + 4 < KT) {
            issue((k + 4) % ASTAGES, k + 4);
            issue((k + 5) % ASTAGES, k + 5);
        }
        cpcommit();
        compute(k % ASTAGES);
        compute((k + 1) % ASTAGES);
    }

    // ---- k-partial reduction through retired stage smem ----
    float* red = (float*)sm;                   // 128 x 80 fp32 = 40KB
    __syncthreads();
    if (kq == 1) {
        #pragma unroll
        for (int c = 0; c < 10; c++) {
            #pragma unroll
            for (int q = 0; q < 4; q++) {
                int row = wm * 16 + g + ((q >> 1) << 3);
                int col = c * 8 + 2 * t + (q & 1);
                red[row * 80 + col] = acc[c][q];
            }
        }
    }
    __syncthreads();
    if (kq == 0) {
        #pragma unroll
        for (int c = 0; c < 10; c++) {
            #pragma unroll
            for (int q = 0; q < 4; q++) {
                int row = wm * 16 + g + ((q >> 1) << 3);
                int col = c * 8 + 2 * t + (q & 1);
                acc[c][q] += red[row * 80 + col];
            }
        }
        if (t == 0) {
            Zs[wm * 16 + g]     = acc[8][0];
            Zs[wm * 16 + g + 8] = acc[8][2];
        }
    }
    __syncthreads();
    if (kq == 0) {
        int rl0 = wm * 16 + g;
        float rz0 = 1.0f / (4096.0f * Zs[rl0]);
        float rz1 = 1.0f / (4096.0f * Zs[rl0 + 8]);
        long ro0 = ((long)batch * NNODE + mtile * BM + rl0) * 64;
        long ro1 = ro0 + 8 * 64;
        #pragma unroll
        for (int c = 0; c < 8; c++) {
            int colb = c * 8 + 2 * t;
            *(float2*)(OutP + ro0 + colb) =
                make_float2(acc[c][0] * rz0, acc[c][1] * rz0);
            *(float2*)(OutP + ro1 + colb) =
                make_float2(acc[c][2] * rz1, acc[c][3] * rz1);
        }
    }
}

// ------------------------------ launch ------------------------------------
extern "C" void kernel_launch(void* const* d_in, const int* in_sizes, int n_in,
                              void* d_out, int out_size) {
    const float* features = (const float*)d_in[0];
    const float* adj      = (const float*)d_in[1];
    const float* W_fc     = (const float*)d_in[2];
    const float* b_fc     = (const float*)d_in[3];
    const float* W_attn   = (const float*)d_in[4];
    float* out = (float*)d_out;

    cudaFuncSetAttribute(proj_kernel,
                         cudaFuncAttributeMaxDynamicSharedMemorySize, SMEM_PROJ);
    cudaFuncSetAttribute(agg_kernel,
                         cudaFuncAttributeMaxDynamicSharedMemorySize, SMEM_AGG);

    proj_kernel<<<16384 / BM, THREADS, SMEM_PROJ>>>(features, W_fc, b_fc, W_attn);
    agg_kernel<<<dim3(NNODE / BM, BATCH), THREADS, SMEM_AGG>>>(adj, out);
}